// round 14
// baseline (speedup 1.0000x reference)
#include <cuda_runtime.h>
#include <math.h>
#include <stdint.h>
#include <stddef.h>

// Problem constants (shapes fixed by the dataset)
#define NN   10000
#define EE   160000
#define HD   32      // hidden
#define NDD  64      // node_dim
#define EDD  16      // edge_dim
#define MHH  128     // edge mlp hidden

// ---------------- scratch (device globals; no allocation allowed) ----------
__device__ int   g_is64;
__device__ int   g_src[EE], g_dst[EE];
__device__ int   g_cnt_src[NN];
__device__ int   g_off_src[NN + 1];
__device__ int   g_cur_src[NN];
__device__ int   g_ebysrc[EE];
__device__ float g_h[NN * HD];
__device__ float g_z[(size_t)EE * MHH];          // relu(ea@W1+b1)      82 MB
__device__ float g_W2tH[HD * MHH * HD];          // tf32-hi of W2t [j][i*128+m]
__device__ float g_W2tL[HD * MHH * HD];          // tf32-lo residual
__device__ float g_b2t[HD * HD];                 // [j][i] = b2[i*32+j]
__device__ float g_P[(size_t)NN * MHH * HD];     // [n][i*128+m]       164 MB
__device__ float g_agg[NN * HD];                 // scatter-add target

// ---------------- TF32 helpers --------------------------------------------
__device__ __forceinline__ float tf32_hi(float v) {
    uint32_t h;
    asm("cvt.rna.tf32.f32 %0, %1;" : "=r"(h) : "f"(v));
    return __uint_as_float(h);
}
__device__ __forceinline__ void mma_tf32(float* c, const uint32_t* a, const uint32_t* b) {
    asm volatile(
        "mma.sync.aligned.m16n8k8.row.col.f32.tf32.tf32.f32 "
        "{%0,%1,%2,%3}, {%4,%5,%6,%7}, {%8,%9}, {%0,%1,%2,%3};"
        : "+f"(c[0]), "+f"(c[1]), "+f"(c[2]), "+f"(c[3])
        : "r"(a[0]), "r"(a[1]), "r"(a[2]), "r"(a[3]), "r"(b[0]), "r"(b[1]));
}

// ---------------- setup kernels -------------------------------------------

// Detect int64 vs int32 edge_index: int64 little-endian => every odd 32-bit
// word of the first 128 (src) entries is 0 (values in [0,10000)).
__global__ void k_detect(const int* __restrict__ w) {
    __shared__ int ok;
    if (threadIdx.x == 0) ok = 1;
    __syncthreads();
    if (w[2 * threadIdx.x + 1] != 0) atomicExch(&ok, 0);
    __syncthreads();
    if (threadIdx.x == 0) g_is64 = ok;
}

__global__ void k_zero_counts(int nN) {
    int i = blockIdx.x * 256 + threadIdx.x;
    if (i < nN) g_cnt_src[i] = 0;
}

__global__ void k_extract(const int* __restrict__ w, int nE) {
    int e = blockIdx.x * 256 + threadIdx.x;
    if (e >= nE) return;
    int is64 = g_is64;
    int s, d;
    if (is64) { s = w[2 * e]; d = w[2 * (nE + e)]; }
    else      { s = w[e];     d = w[nE + e]; }
    g_src[e] = s; g_dst[e] = d;
    atomicAdd(&g_cnt_src[s], 1);
}

// Fast exclusive scan (src only): per-thread sequential + shuffle block scan.
__global__ __launch_bounds__(1024) void k_scan(int nN) {
    const int CH = 10;
    int tid = threadIdx.x, lane = tid & 31, w = tid >> 5;
    int base = tid * CH;
    int v[CH];
    int s = 0;
#pragma unroll
    for (int q = 0; q < CH; q++) {
        int i = base + q;
        v[q] = (i < nN) ? g_cnt_src[i] : 0;
        s += v[q];
    }
    int sc = s;
#pragma unroll
    for (int o = 1; o < 32; o <<= 1) {
        int t = __shfl_up_sync(0xffffffffu, sc, o);
        if (lane >= o) sc += t;
    }
    __shared__ int wt[32];
    if (lane == 31) wt[w] = sc;
    __syncthreads();
    if (w == 0) {
        int t = wt[lane];
#pragma unroll
        for (int o = 1; o < 32; o <<= 1) {
            int u = __shfl_up_sync(0xffffffffu, t, o);
            if (lane >= o) t += u;
        }
        wt[lane] = t;
    }
    __syncthreads();
    int excl = sc - s + (w ? wt[w - 1] : 0);
    int run = excl;
#pragma unroll
    for (int q = 0; q < CH; q++) {
        int i = base + q;
        if (i < nN) { g_off_src[i] = run; g_cur_src[i] = run; run += v[q]; }
    }
    if (tid == 1023) g_off_src[nN] = excl + s;
}

__global__ void k_fill(int nE) {
    int e = blockIdx.x * 256 + threadIdx.x;
    if (e >= nE) return;
    int s = g_src[e];
    int p = atomicAdd(&g_cur_src[s], 1); g_ebysrc[p] = e;
}

// W2t split into tf32 hi/lo: layout [j*4096 + i*128 + m] = W2[m*1024+i*32+j].
// b2t[j*32+i] = b2[i*32+j]
__global__ void k_w2t(const float* __restrict__ W2, const float* __restrict__ b2) {
    int t = blockIdx.x * 256 + threadIdx.x;
    if (t < HD * MHH * HD) {
        int j = t >> 12, i = (t >> 7) & 31, m = t & 127;
        float v = W2[m * 1024 + i * 32 + j];
        float hi = tf32_hi(v);
        g_W2tH[t] = hi;
        g_W2tL[t] = tf32_hi(v - hi);
    }
    int t2 = t - HD * MHH * HD;
    if (t2 >= 0 && t2 < HD * HD) {
        int j = t2 >> 5, i = t2 & 31;
        g_b2t[t2] = b2[i * 32 + j];
    }
}

// h0 = x @ Wp + bp   (warp per node)
__global__ __launch_bounds__(256) void k_h0(const float* __restrict__ x,
                                            const float* __restrict__ Wp,
                                            const float* __restrict__ bp, int nN) {
    __shared__ float Ws[NDD * HD];
    __shared__ float bs[HD];
    int tid = threadIdx.x;
    for (int i = tid; i < NDD * HD; i += 256) Ws[i] = Wp[i];
    if (tid < HD) bs[tid] = bp[tid];
    __syncthreads();
    int w = tid >> 5, lane = tid & 31;
    int n = blockIdx.x * 8 + w;
    if (n >= nN) return;
    float x0 = x[n * 64 + lane], x1 = x[n * 64 + 32 + lane];
    float acc = bs[lane];
#pragma unroll
    for (int j = 0; j < 32; j++) acc += __shfl_sync(0xffffffffu, x0, j) * Ws[j * 32 + lane];
#pragma unroll
    for (int j = 0; j < 32; j++) acc += __shfl_sync(0xffffffffu, x1, j) * Ws[(32 + j) * 32 + lane];
    g_h[n * 32 + lane] = acc;
}

// z = relu(ea @ W1 + b1)   (warp per edge)
__global__ __launch_bounds__(256) void k_z(const float* __restrict__ ea,
                                           const float* __restrict__ W1,
                                           const float* __restrict__ b1, int nE) {
    __shared__ float Ws[EDD * MHH];
    __shared__ float bs[MHH];
    int tid = threadIdx.x;
    for (int i = tid; i < EDD * MHH; i += 256) Ws[i] = W1[i];
    if (tid < MHH) bs[tid] = b1[tid];
    __syncthreads();
    int w = tid >> 5, lane = tid & 31;
    int e = blockIdx.x * 8 + w;
    if (e >= nE) return;
    float a0 = (lane < 16) ? ea[e * 16 + lane] : 0.f;
    float acc0 = bs[lane], acc1 = bs[32 + lane], acc2 = bs[64 + lane], acc3 = bs[96 + lane];
#pragma unroll
    for (int j = 0; j < 16; j++) {
        float a = __shfl_sync(0xffffffffu, a0, j);
        acc0 += a * Ws[j * 128 + lane];
        acc1 += a * Ws[j * 128 + 32 + lane];
        acc2 += a * Ws[j * 128 + 64 + lane];
        acc3 += a * Ws[j * 128 + 96 + lane];
    }
    float* zp = &g_z[(size_t)e * 128];
    zp[lane]      = fmaxf(acc0, 0.f);
    zp[32 + lane] = fmaxf(acc1, 0.f);
    zp[64 + lane] = fmaxf(acc2, 0.f);
    zp[96 + lane] = fmaxf(acc3, 0.f);
}

// ---------------- per-step kernels ----------------------------------------

// P = H (nN x 32) @ W2t (32 x 4096) on tensor cores, 3xTF32 split, splits
// precomputed outside the mainloop. R14: each block processes 4 bm-subtiles
// (64 rows each) with Bs (W2t hi/lo chunk) loaded into smem ONCE — the
// dominant L2-latency prologue is amortized 4x, block count drops 5024->1280.
// Warp tile 32x32, launch_bounds(256,2) -> 2 blocks/SM.
// blockIdx.x==0 blocks also zero their 256 g_agg rows.
__global__ __launch_bounds__(256, 2) void k_P(int nN) {
    extern __shared__ float sm[];
    float* BsH = sm;                       // [32][136]
    float* BsL = BsH + 32 * 136;           // [32][136]
    float* AsH = BsL + 32 * 136;           // [64][36]
    float* AsL = AsH + 64 * 36;            // [64][36]
    int tid = threadIdx.x;
    int bn = blockIdx.x * 128;
    int bm0 = blockIdx.y * 256;

    if (blockIdx.x == 0) {                 // zero agg rows for this 256-row stripe
        int base = bm0 * 32;
        for (int idx = tid; idx < 8192; idx += 256)
            if (base + idx < nN * 32) g_agg[base + idx] = 0.f;
    }

    for (int idx = tid; idx < 32 * 128; idx += 256) {
        int k = idx >> 7, c = idx & 127;
        BsH[k * 136 + c] = g_W2tH[k * 4096 + bn + c];
        BsL[k * 136 + c] = g_W2tL[k * 4096 + bn + c];
    }

    int warp = tid >> 5, lane = tid & 31;
    int g = lane >> 2, tg = lane & 3;
    int wm = (warp >> 2) * 32, wn = (warp & 3) * 32;

#pragma unroll 1
    for (int t = 0; t < 4; t++) {
        int bm = bm0 + t * 64;
        if (bm >= nN) break;

        for (int idx = tid; idx < 64 * 32; idx += 256) {
            int r = idx >> 5, k = idx & 31;
            int n = bm + r;
            float v = (n < nN) ? g_h[n * 32 + k] : 0.f;
            float hi = tf32_hi(v);
            AsH[r * 36 + k] = hi;
            AsL[r * 36 + k] = tf32_hi(v - hi);
        }
        __syncthreads();

        float acc[2][4][4] = {};
#pragma unroll
        for (int k0 = 0; k0 < 32; k0 += 8) {
            uint32_t ah[2][4], al[2][4];
#pragma unroll
            for (int mf = 0; mf < 2; mf++) {
                int r = wm + mf * 16 + g;
                ah[mf][0] = __float_as_uint(AsH[r * 36 + k0 + tg]);
                ah[mf][1] = __float_as_uint(AsH[(r + 8) * 36 + k0 + tg]);
                ah[mf][2] = __float_as_uint(AsH[r * 36 + k0 + tg + 4]);
                ah[mf][3] = __float_as_uint(AsH[(r + 8) * 36 + k0 + tg + 4]);
                al[mf][0] = __float_as_uint(AsL[r * 36 + k0 + tg]);
                al[mf][1] = __float_as_uint(AsL[(r + 8) * 36 + k0 + tg]);
                al[mf][2] = __float_as_uint(AsL[r * 36 + k0 + tg + 4]);
                al[mf][3] = __float_as_uint(AsL[(r + 8) * 36 + k0 + tg + 4]);
            }
            uint32_t bh[4][2], bl[4][2];
#pragma unroll
            for (int nf = 0; nf < 4; nf++) {
                int c = wn + nf * 8 + g;
                bh[nf][0] = __float_as_uint(BsH[(k0 + tg) * 136 + c]);
                bh[nf][1] = __float_as_uint(BsH[(k0 + tg + 4) * 136 + c]);
                bl[nf][0] = __float_as_uint(BsL[(k0 + tg) * 136 + c]);
                bl[nf][1] = __float_as_uint(BsL[(k0 + tg + 4) * 136 + c]);
            }
#pragma unroll
            for (int mf = 0; mf < 2; mf++)
#pragma unroll
                for (int nf = 0; nf < 4; nf++) {
                    mma_tf32(acc[mf][nf], ah[mf], bh[nf]);
                    mma_tf32(acc[mf][nf], ah[mf], bl[nf]);
                    mma_tf32(acc[mf][nf], al[mf], bh[nf]);
                }
        }

#pragma unroll
        for (int mf = 0; mf < 2; mf++) {
            int r0 = bm + wm + mf * 16 + g;
#pragma unroll
            for (int nf = 0; nf < 4; nf++) {
                int c = bn + wn + nf * 8 + 2 * tg;
                if (r0 < nN)
                    *(float2*)&g_P[(size_t)r0 * 4096 + c] = make_float2(acc[mf][nf][0], acc[mf][nf][1]);
                if (r0 + 8 < nN)
                    *(float2*)&g_P[(size_t)(r0 + 8) * 4096 + c] = make_float2(acc[mf][nf][2], acc[mf][nf][3]);
            }
        }
        __syncthreads();     // protect As before next subtile overwrites it
    }
}
#define KP_SMEM ((2 * 32 * 136 + 2 * 64 * 36) * 4)

// For each src node: stage its 16KB P block in smem once, then for every
// out-edge compute msg[e,i] = C[src,i] + sum_m z[e,m]*P[src,i,m] and
// scatter-add straight into g_agg[dst]. R14: 8-edge groups per Ps pass
// (was 4) -> half the Ps re-reads per node, 0.375 wf/FFMA (was 0.5).
__global__ __launch_bounds__(128) void k_msg() {
    int n = blockIdx.x;
    int off = g_off_src[n];
    int d = g_off_src[n + 1] - off;
    if (d == 0) return;
    __shared__ float Ps[32 * 132];        // [i][m], row stride 132 floats
    __shared__ float zb[4][8][128];       // [warp][edge][m]
    __shared__ float Cn[32];
    int tid = threadIdx.x, w = tid >> 5, lane = tid & 31;
    const float4* Pg = (const float4*)&g_P[(size_t)n * 4096];
    for (int t = tid; t < 1024; t += 128) {
        int i = t >> 5, m4 = t & 31;
        *(float4*)&Ps[i * 132 + m4 * 4] = Pg[t];
    }
    if (tid < 32) {
        float acc = 0.f;
#pragma unroll
        for (int j = 0; j < 32; j++) acc += g_h[n * 32 + j] * g_b2t[j * 32 + tid];
        Cn[tid] = acc;
    }
    __syncthreads();

    for (int base = w * 8; base < d; base += 32) {
        int cnt = d - base; if (cnt > 8) cnt = 8;
        int eidx[8];
#pragma unroll
        for (int k = 0; k < 8; k++) {
            if (k < cnt) {
                int e = g_ebysrc[off + base + k];
                eidx[k] = e;
                const float4* zp4 = (const float4*)&g_z[(size_t)e * 128];
                *(float4*)&zb[w][k][lane * 4] = zp4[lane];
            }
        }
        __syncwarp();
        float acc[8];
#pragma unroll
        for (int k = 0; k < 8; k++) acc[k] = Cn[lane];
        const float4* prow = (const float4*)&Ps[lane * 132];
#pragma unroll 4
        for (int m4 = 0; m4 < 32; m4++) {
            float4 p = prow[m4];
#pragma unroll
            for (int k = 0; k < 8; k++) {
                float4 zv = *(const float4*)&zb[w][k][m4 * 4];
                acc[k] += p.x * zv.x + p.y * zv.y + p.z * zv.z + p.w * zv.w;
            }
        }
#pragma unroll
        for (int k = 0; k < 8; k++)
            if (k < cnt) {
                int dn = g_dst[eidx[k]];
                atomicAdd(&g_agg[dn * 32 + lane], acc[k]);
            }
        __syncwarp();
    }
}

// GRUCell (torch layout [r,z,n]) reading pre-aggregated g_agg.
__global__ __launch_bounds__(256) void k_gru(const float* __restrict__ wih,
                                             const float* __restrict__ whh,
                                             const float* __restrict__ bih,
                                             const float* __restrict__ bhh,
                                             float* __restrict__ out, int nN) {
    __shared__ float wi[32 * 96];
    __shared__ float wh[32 * 96];
    __shared__ float bi[96], bh[96];
    int tid = threadIdx.x;
    for (int idx = tid; idx < 3072; idx += 256) {
        int k = idx >> 5, j = idx & 31;
        wi[j * 96 + k] = wih[idx];
        wh[j * 96 + k] = whh[idx];
    }
    if (tid < 96) { bi[tid] = bih[tid]; bh[tid] = bhh[tid]; }
    __syncthreads();
    int w = tid >> 5, lane = tid & 31;
    int n = blockIdx.x * 8 + w;
    if (n >= nN) return;

    float av = g_agg[n * 32 + lane];
    float hv = g_h[n * 32 + lane];

    float gi0 = bi[lane], gi1 = bi[32 + lane], gi2 = bi[64 + lane];
    float gh0 = bh[lane], gh1 = bh[32 + lane], gh2 = bh[64 + lane];
#pragma unroll
    for (int j = 0; j < 32; j++) {
        float a = __shfl_sync(0xffffffffu, av, j);
        float h = __shfl_sync(0xffffffffu, hv, j);
        gi0 += a * wi[j * 96 + lane];
        gi1 += a * wi[j * 96 + 32 + lane];
        gi2 += a * wi[j * 96 + 64 + lane];
        gh0 += h * wh[j * 96 + lane];
        gh1 += h * wh[j * 96 + 32 + lane];
        gh2 += h * wh[j * 96 + 64 + lane];
    }
    float r  = 1.f / (1.f + expf(-(gi0 + gh0)));
    float zz = 1.f / (1.f + expf(-(gi1 + gh1)));
    float nn = tanhf(gi2 + r * gh2);
    float hn = (1.f - zz) * nn + zz * hv;
    g_h[n * 32 + lane] = hn;
    out[n * 32 + lane] = hn;
}

// ---------------- launch ---------------------------------------------------

extern "C" void kernel_launch(void* const* d_in, const int* in_sizes, int n_in,
                              void* d_out, int out_size) {
    const float* x   = (const float*)d_in[0];
    const int*   ei  = (const int*)d_in[1];
    const float* ea  = (const float*)d_in[2];
    const float* Wp  = (const float*)d_in[3];
    const float* bp  = (const float*)d_in[4];
    const float* W1  = (const float*)d_in[5];
    const float* b1  = (const float*)d_in[6];
    const float* W2  = (const float*)d_in[7];
    const float* b2  = (const float*)d_in[8];
    const float* wih = (const float*)d_in[9];
    const float* whh = (const float*)d_in[10];
    const float* bih = (const float*)d_in[11];
    const float* bhh = (const float*)d_in[12];
    float* out = (float*)d_out;

    int nN = in_sizes[0] / NDD; if (nN > NN) nN = NN;
    int nE = in_sizes[2] / EDD; if (nE > EE) nE = EE;

    cudaFuncSetAttribute(k_P, cudaFuncAttributeMaxDynamicSharedMemorySize, KP_SMEM);

    dim3 gP(32, (nN + 255) / 256);

    // CSR-independent setup first so ncu's capture slot lands on k_P.
    k_w2t<<<(HD * MHH * HD + HD * HD + 255) / 256, 256>>>(W2, b2);
    k_h0<<<(nN + 7) / 8, 256>>>(x, Wp, bp, nN);
    k_z<<<(nE + 7) / 8, 256>>>(ea, W1, b1, nE);
    k_P<<<gP, 256, KP_SMEM>>>(nN);            // step 1 P + agg zero

    // CSR build (src only; needed before first k_msg)
    k_zero_counts<<<(nN + 255) / 256, 256>>>(nN);
    k_detect<<<1, 128>>>(ei);
    k_extract<<<(nE + 255) / 256, 256>>>(ei, nE);
    k_scan<<<1, 1024>>>(nN);
    k_fill<<<(nE + 255) / 256, 256>>>(nE);

    // step 1 remainder
    k_msg<<<nN, 128>>>();
    k_gru<<<(nN + 7) / 8, 256>>>(wih, whh, bih, bhh, out, nN);

    // steps 2..3
    for (int step = 1; step < 3; step++) {
        k_P<<<gP, 256, KP_SMEM>>>(nN);
        k_msg<<<nN, 128>>>();
        k_gru<<<(nN + 7) / 8, 256>>>(wih, whh, bih, bhh, out, nN);
    }
}

// round 15
// speedup vs baseline: 1.6765x; 1.6765x over previous
#include <cuda_runtime.h>
#include <math.h>
#include <stdint.h>
#include <stddef.h>

// Problem constants (shapes fixed by the dataset)
#define NN   10000
#define EE   160000
#define HD   32      // hidden
#define NDD  64      // node_dim
#define EDD  16      // edge_dim
#define MHH  128     // edge mlp hidden

// ---------------- scratch (device globals; no allocation allowed) ----------
__device__ int   g_is64;
__device__ int   g_src[EE], g_dst[EE];
__device__ int   g_cnt_src[NN];
__device__ int   g_off_src[NN + 1];
__device__ int   g_cur_src[NN];
__device__ int   g_ebysrc[EE];
__device__ float g_h[NN * HD];
__device__ float g_z[(size_t)EE * MHH];          // relu(ea@W1+b1)      82 MB
__device__ float g_W2tH[HD * MHH * HD];          // tf32-hi of W2t [j][i*128+m]
__device__ float g_W2tL[HD * MHH * HD];          // tf32-lo residual
__device__ float g_b2t[HD * HD];                 // [j][i] = b2[i*32+j]
__device__ float g_P[(size_t)NN * MHH * HD];     // [n][i*128+m]       164 MB
__device__ float g_agg[NN * HD];                 // scatter-add target

// ---------------- TF32 / f32x2 helpers -------------------------------------
__device__ __forceinline__ float tf32_hi(float v) {
    uint32_t h;
    asm("cvt.rna.tf32.f32 %0, %1;" : "=r"(h) : "f"(v));
    return __uint_as_float(h);
}
__device__ __forceinline__ void mma_tf32(float* c, const uint32_t* a, const uint32_t* b) {
    asm volatile(
        "mma.sync.aligned.m16n8k8.row.col.f32.tf32.tf32.f32 "
        "{%0,%1,%2,%3}, {%4,%5,%6,%7}, {%8,%9}, {%0,%1,%2,%3};"
        : "+f"(c[0]), "+f"(c[1]), "+f"(c[2]), "+f"(c[3])
        : "r"(a[0]), "r"(a[1]), "r"(a[2]), "r"(a[3]), "r"(b[0]), "r"(b[1]));
}
__device__ __forceinline__ unsigned long long fma2(unsigned long long a,
                                                   unsigned long long b,
                                                   unsigned long long c) {
    unsigned long long d;
    asm("fma.rn.f32x2 %0, %1, %2, %3;" : "=l"(d) : "l"(a), "l"(b), "l"(c));
    return d;
}
__device__ __forceinline__ unsigned long long addf2(unsigned long long a,
                                                    unsigned long long b) {
    unsigned long long d;
    asm("add.rn.f32x2 %0, %1, %2;" : "=l"(d) : "l"(a), "l"(b));
    return d;
}

// ---------------- setup kernels -------------------------------------------

// Detect int64 vs int32 edge_index: int64 little-endian => every odd 32-bit
// word of the first 128 (src) entries is 0 (values in [0,10000)).
__global__ void k_detect(const int* __restrict__ w) {
    __shared__ int ok;
    if (threadIdx.x == 0) ok = 1;
    __syncthreads();
    if (w[2 * threadIdx.x + 1] != 0) atomicExch(&ok, 0);
    __syncthreads();
    if (threadIdx.x == 0) g_is64 = ok;
}

__global__ void k_zero_counts(int nN) {
    int i = blockIdx.x * 256 + threadIdx.x;
    if (i < nN) g_cnt_src[i] = 0;
}

__global__ void k_extract(const int* __restrict__ w, int nE) {
    int e = blockIdx.x * 256 + threadIdx.x;
    if (e >= nE) return;
    int is64 = g_is64;
    int s, d;
    if (is64) { s = w[2 * e]; d = w[2 * (nE + e)]; }
    else      { s = w[e];     d = w[nE + e]; }
    g_src[e] = s; g_dst[e] = d;
    atomicAdd(&g_cnt_src[s], 1);
}

// Fast exclusive scan (src only): per-thread sequential + shuffle block scan.
__global__ __launch_bounds__(1024) void k_scan(int nN) {
    const int CH = 10;
    int tid = threadIdx.x, lane = tid & 31, w = tid >> 5;
    int base = tid * CH;
    int v[CH];
    int s = 0;
#pragma unroll
    for (int q = 0; q < CH; q++) {
        int i = base + q;
        v[q] = (i < nN) ? g_cnt_src[i] : 0;
        s += v[q];
    }
    int sc = s;
#pragma unroll
    for (int o = 1; o < 32; o <<= 1) {
        int t = __shfl_up_sync(0xffffffffu, sc, o);
        if (lane >= o) sc += t;
    }
    __shared__ int wt[32];
    if (lane == 31) wt[w] = sc;
    __syncthreads();
    if (w == 0) {
        int t = wt[lane];
#pragma unroll
        for (int o = 1; o < 32; o <<= 1) {
            int u = __shfl_up_sync(0xffffffffu, t, o);
            if (lane >= o) t += u;
        }
        wt[lane] = t;
    }
    __syncthreads();
    int excl = sc - s + (w ? wt[w - 1] : 0);
    int run = excl;
#pragma unroll
    for (int q = 0; q < CH; q++) {
        int i = base + q;
        if (i < nN) { g_off_src[i] = run; g_cur_src[i] = run; run += v[q]; }
    }
    if (tid == 1023) g_off_src[nN] = excl + s;
}

__global__ void k_fill(int nE) {
    int e = blockIdx.x * 256 + threadIdx.x;
    if (e >= nE) return;
    int s = g_src[e];
    int p = atomicAdd(&g_cur_src[s], 1); g_ebysrc[p] = e;
}

// W2t split into tf32 hi/lo: layout [j*4096 + i*128 + m] = W2[m*1024+i*32+j].
// b2t[j*32+i] = b2[i*32+j]
__global__ void k_w2t(const float* __restrict__ W2, const float* __restrict__ b2) {
    int t = blockIdx.x * 256 + threadIdx.x;
    if (t < HD * MHH * HD) {
        int j = t >> 12, i = (t >> 7) & 31, m = t & 127;
        float v = W2[m * 1024 + i * 32 + j];
        float hi = tf32_hi(v);
        g_W2tH[t] = hi;
        g_W2tL[t] = tf32_hi(v - hi);
    }
    int t2 = t - HD * MHH * HD;
    if (t2 >= 0 && t2 < HD * HD) {
        int j = t2 >> 5, i = t2 & 31;
        g_b2t[t2] = b2[i * 32 + j];
    }
}

// h0 = x @ Wp + bp   (warp per node)
__global__ __launch_bounds__(256) void k_h0(const float* __restrict__ x,
                                            const float* __restrict__ Wp,
                                            const float* __restrict__ bp, int nN) {
    __shared__ float Ws[NDD * HD];
    __shared__ float bs[HD];
    int tid = threadIdx.x;
    for (int i = tid; i < NDD * HD; i += 256) Ws[i] = Wp[i];
    if (tid < HD) bs[tid] = bp[tid];
    __syncthreads();
    int w = tid >> 5, lane = tid & 31;
    int n = blockIdx.x * 8 + w;
    if (n >= nN) return;
    float x0 = x[n * 64 + lane], x1 = x[n * 64 + 32 + lane];
    float acc = bs[lane];
#pragma unroll
    for (int j = 0; j < 32; j++) acc += __shfl_sync(0xffffffffu, x0, j) * Ws[j * 32 + lane];
#pragma unroll
    for (int j = 0; j < 32; j++) acc += __shfl_sync(0xffffffffu, x1, j) * Ws[(32 + j) * 32 + lane];
    g_h[n * 32 + lane] = acc;
}

// z = relu(ea @ W1 + b1)   (warp per edge)
__global__ __launch_bounds__(256) void k_z(const float* __restrict__ ea,
                                           const float* __restrict__ W1,
                                           const float* __restrict__ b1, int nE) {
    __shared__ float Ws[EDD * MHH];
    __shared__ float bs[MHH];
    int tid = threadIdx.x;
    for (int i = tid; i < EDD * MHH; i += 256) Ws[i] = W1[i];
    if (tid < MHH) bs[tid] = b1[tid];
    __syncthreads();
    int w = tid >> 5, lane = tid & 31;
    int e = blockIdx.x * 8 + w;
    if (e >= nE) return;
    float a0 = (lane < 16) ? ea[e * 16 + lane] : 0.f;
    float acc0 = bs[lane], acc1 = bs[32 + lane], acc2 = bs[64 + lane], acc3 = bs[96 + lane];
#pragma unroll
    for (int j = 0; j < 16; j++) {
        float a = __shfl_sync(0xffffffffu, a0, j);
        acc0 += a * Ws[j * 128 + lane];
        acc1 += a * Ws[j * 128 + 32 + lane];
        acc2 += a * Ws[j * 128 + 64 + lane];
        acc3 += a * Ws[j * 128 + 96 + lane];
    }
    float* zp = &g_z[(size_t)e * 128];
    zp[lane]      = fmaxf(acc0, 0.f);
    zp[32 + lane] = fmaxf(acc1, 0.f);
    zp[64 + lane] = fmaxf(acc2, 0.f);
    zp[96 + lane] = fmaxf(acc3, 0.f);
}

// ---------------- per-step kernels ----------------------------------------

// P = H (nN x 32) @ W2t (32 x 4096) on tensor cores, 3xTF32 split, splits
// precomputed outside the mainloop. Each block processes 4 bm-subtiles
// (64 rows each) with Bs (W2t hi/lo chunk) loaded into smem ONCE.
// Warp tile 32x32, launch_bounds(256,2). (R14-verified: 123 us.)
__global__ __launch_bounds__(256, 2) void k_P(int nN) {
    extern __shared__ float sm[];
    float* BsH = sm;                       // [32][136]
    float* BsL = BsH + 32 * 136;           // [32][136]
    float* AsH = BsL + 32 * 136;           // [64][36]
    float* AsL = AsH + 64 * 36;            // [64][36]
    int tid = threadIdx.x;
    int bn = blockIdx.x * 128;
    int bm0 = blockIdx.y * 256;

    if (blockIdx.x == 0) {                 // zero agg rows for this 256-row stripe
        int base = bm0 * 32;
        for (int idx = tid; idx < 8192; idx += 256)
            if (base + idx < nN * 32) g_agg[base + idx] = 0.f;
    }

    for (int idx = tid; idx < 32 * 128; idx += 256) {
        int k = idx >> 7, c = idx & 127;
        BsH[k * 136 + c] = g_W2tH[k * 4096 + bn + c];
        BsL[k * 136 + c] = g_W2tL[k * 4096 + bn + c];
    }

    int warp = tid >> 5, lane = tid & 31;
    int g = lane >> 2, tg = lane & 3;
    int wm = (warp >> 2) * 32, wn = (warp & 3) * 32;

#pragma unroll 1
    for (int t = 0; t < 4; t++) {
        int bm = bm0 + t * 64;
        if (bm >= nN) break;

        for (int idx = tid; idx < 64 * 32; idx += 256) {
            int r = idx >> 5, k = idx & 31;
            int n = bm + r;
            float v = (n < nN) ? g_h[n * 32 + k] : 0.f;
            float hi = tf32_hi(v);
            AsH[r * 36 + k] = hi;
            AsL[r * 36 + k] = tf32_hi(v - hi);
        }
        __syncthreads();

        float acc[2][4][4] = {};
#pragma unroll
        for (int k0 = 0; k0 < 32; k0 += 8) {
            uint32_t ah[2][4], al[2][4];
#pragma unroll
            for (int mf = 0; mf < 2; mf++) {
                int r = wm + mf * 16 + g;
                ah[mf][0] = __float_as_uint(AsH[r * 36 + k0 + tg]);
                ah[mf][1] = __float_as_uint(AsH[(r + 8) * 36 + k0 + tg]);
                ah[mf][2] = __float_as_uint(AsH[r * 36 + k0 + tg + 4]);
                ah[mf][3] = __float_as_uint(AsH[(r + 8) * 36 + k0 + tg + 4]);
                al[mf][0] = __float_as_uint(AsL[r * 36 + k0 + tg]);
                al[mf][1] = __float_as_uint(AsL[(r + 8) * 36 + k0 + tg]);
                al[mf][2] = __float_as_uint(AsL[r * 36 + k0 + tg + 4]);
                al[mf][3] = __float_as_uint(AsL[(r + 8) * 36 + k0 + tg + 4]);
            }
            uint32_t bh[4][2], bl[4][2];
#pragma unroll
            for (int nf = 0; nf < 4; nf++) {
                int c = wn + nf * 8 + g;
                bh[nf][0] = __float_as_uint(BsH[(k0 + tg) * 136 + c]);
                bh[nf][1] = __float_as_uint(BsH[(k0 + tg + 4) * 136 + c]);
                bl[nf][0] = __float_as_uint(BsL[(k0 + tg) * 136 + c]);
                bl[nf][1] = __float_as_uint(BsL[(k0 + tg + 4) * 136 + c]);
            }
#pragma unroll
            for (int mf = 0; mf < 2; mf++)
#pragma unroll
                for (int nf = 0; nf < 4; nf++) {
                    mma_tf32(acc[mf][nf], ah[mf], bh[nf]);
                    mma_tf32(acc[mf][nf], ah[mf], bl[nf]);
                    mma_tf32(acc[mf][nf], al[mf], bh[nf]);
                }
        }

#pragma unroll
        for (int mf = 0; mf < 2; mf++) {
            int r0 = bm + wm + mf * 16 + g;
#pragma unroll
            for (int nf = 0; nf < 4; nf++) {
                int c = bn + wn + nf * 8 + 2 * tg;
                if (r0 < nN)
                    *(float2*)&g_P[(size_t)r0 * 4096 + c] = make_float2(acc[mf][nf][0], acc[mf][nf][1]);
                if (r0 + 8 < nN)
                    *(float2*)&g_P[(size_t)(r0 + 8) * 4096 + c] = make_float2(acc[mf][nf][2], acc[mf][nf][3]);
            }
        }
        __syncthreads();     // protect As before next subtile overwrites it
    }
}
#define KP_SMEM ((2 * 32 * 136 + 2 * 64 * 36) * 4)

// For each src node: stage its 16KB P block in smem once, then for every
// out-edge compute msg[e,i] = C[src,i] + sum_m z[e,m]*P[src,i,m] and
// scatter-add into g_agg[dst].
// R15: back to 4-edge warp groups (4 warps x 4 = 16 = mean degree, full warp
// utilization) and the float4 dot packed as 2x fma.rn.f32x2 (issue-bound
// kernel: 21 -> 13 instr per m4 per warp).
__global__ __launch_bounds__(128) void k_msg() {
    int n = blockIdx.x;
    int off = g_off_src[n];
    int d = g_off_src[n + 1] - off;
    if (d == 0) return;
    __shared__ float Ps[32 * 132];        // [i][m], row stride 132 floats
    __shared__ float zb[4][4][128];       // [warp][edge][m]
    __shared__ float Cn[32];
    int tid = threadIdx.x, w = tid >> 5, lane = tid & 31;
    const float4* Pg = (const float4*)&g_P[(size_t)n * 4096];
    for (int t = tid; t < 1024; t += 128) {
        int i = t >> 5, m4 = t & 31;
        *(float4*)&Ps[i * 132 + m4 * 4] = Pg[t];
    }
    if (tid < 32) {
        float acc = 0.f;
#pragma unroll
        for (int j = 0; j < 32; j++) acc += g_h[n * 32 + j] * g_b2t[j * 32 + tid];
        Cn[tid] = acc;
    }
    __syncthreads();

    for (int base = w * 4; base < d; base += 16) {
        int cnt = min(4, d - base);
        int eidx[4];
#pragma unroll
        for (int k = 0; k < 4; k++) {
            if (k < cnt) {
                int e = g_ebysrc[off + base + k];
                eidx[k] = e;
                const float4* zp4 = (const float4*)&g_z[(size_t)e * 128];
                *(float4*)&zb[w][k][lane * 4] = zp4[lane];
            }
        }
        __syncwarp();
        unsigned long long a0[4], a1[4];
#pragma unroll
        for (int k = 0; k < 4; k++) { a0[k] = 0ull; a1[k] = 0ull; }
        const float* prow = &Ps[lane * 132];
#pragma unroll 8
        for (int m4 = 0; m4 < 32; m4++) {
            ulonglong2 pp = *(const ulonglong2*)(prow + m4 * 4);
#pragma unroll
            for (int k = 0; k < 4; k++) {
                ulonglong2 zz = *(const ulonglong2*)&zb[w][k][m4 * 4];
                a0[k] = fma2(pp.x, zz.x, a0[k]);
                a1[k] = fma2(pp.y, zz.y, a1[k]);
            }
        }
#pragma unroll
        for (int k = 0; k < 4; k++)
            if (k < cnt) {
                unsigned long long s = addf2(a0[k], a1[k]);
                union { unsigned long long u; float2 f; } cv; cv.u = s;
                int dn = g_dst[eidx[k]];
                atomicAdd(&g_agg[dn * 32 + lane], cv.f.x + cv.f.y + Cn[lane]);
            }
        __syncwarp();
    }
}

// GRUCell (torch layout [r,z,n]) reading pre-aggregated g_agg.
__global__ __launch_bounds__(256) void k_gru(const float* __restrict__ wih,
                                             const float* __restrict__ whh,
                                             const float* __restrict__ bih,
                                             const float* __restrict__ bhh,
                                             float* __restrict__ out, int nN) {
    __shared__ float wi[32 * 96];
    __shared__ float wh[32 * 96];
    __shared__ float bi[96], bh[96];
    int tid = threadIdx.x;
    for (int idx = tid; idx < 3072; idx += 256) {
        int k = idx >> 5, j = idx & 31;
        wi[j * 96 + k] = wih[idx];
        wh[j * 96 + k] = whh[idx];
    }
    if (tid < 96) { bi[tid] = bih[tid]; bh[tid] = bhh[tid]; }
    __syncthreads();
    int w = tid >> 5, lane = tid & 31;
    int n = blockIdx.x * 8 + w;
    if (n >= nN) return;

    float av = g_agg[n * 32 + lane];
    float hv = g_h[n * 32 + lane];

    float gi0 = bi[lane], gi1 = bi[32 + lane], gi2 = bi[64 + lane];
    float gh0 = bh[lane], gh1 = bh[32 + lane], gh2 = bh[64 + lane];
#pragma unroll
    for (int j = 0; j < 32; j++) {
        float a = __shfl_sync(0xffffffffu, av, j);
        float h = __shfl_sync(0xffffffffu, hv, j);
        gi0 += a * wi[j * 96 + lane];
        gi1 += a * wi[j * 96 + 32 + lane];
        gi2 += a * wi[j * 96 + 64 + lane];
        gh0 += h * wh[j * 96 + lane];
        gh1 += h * wh[j * 96 + 32 + lane];
        gh2 += h * wh[j * 96 + 64 + lane];
    }
    float r  = 1.f / (1.f + expf(-(gi0 + gh0)));
    float zz = 1.f / (1.f + expf(-(gi1 + gh1)));
    float nn = tanhf(gi2 + r * gh2);
    float hn = (1.f - zz) * nn + zz * hv;
    g_h[n * 32 + lane] = hn;
    out[n * 32 + lane] = hn;
}

// ---------------- launch ---------------------------------------------------

extern "C" void kernel_launch(void* const* d_in, const int* in_sizes, int n_in,
                              void* d_out, int out_size) {
    const float* x   = (const float*)d_in[0];
    const int*   ei  = (const int*)d_in[1];
    const float* ea  = (const float*)d_in[2];
    const float* Wp  = (const float*)d_in[3];
    const float* bp  = (const float*)d_in[4];
    const float* W1  = (const float*)d_in[5];
    const float* b1  = (const float*)d_in[6];
    const float* W2  = (const float*)d_in[7];
    const float* b2  = (const float*)d_in[8];
    const float* wih = (const float*)d_in[9];
    const float* whh = (const float*)d_in[10];
    const float* bih = (const float*)d_in[11];
    const float* bhh = (const float*)d_in[12];
    float* out = (float*)d_out;

    int nN = in_sizes[0] / NDD; if (nN > NN) nN = NN;
    int nE = in_sizes[2] / EDD; if (nE > EE) nE = EE;

    cudaFuncSetAttribute(k_P, cudaFuncAttributeMaxDynamicSharedMemorySize, KP_SMEM);

    dim3 gP(32, (nN + 255) / 256);

    // CSR-independent setup first so ncu's capture slot lands on k_P.
    k_w2t<<<(HD * MHH * HD + HD * HD + 255) / 256, 256>>>(W2, b2);
    k_h0<<<(nN + 7) / 8, 256>>>(x, Wp, bp, nN);
    k_z<<<(nE + 7) / 8, 256>>>(ea, W1, b1, nE);
    k_P<<<gP, 256, KP_SMEM>>>(nN);            // step 1 P + agg zero

    // CSR build (src only; needed before first k_msg)
    k_zero_counts<<<(nN + 255) / 256, 256>>>(nN);
    k_detect<<<1, 128>>>(ei);
    k_extract<<<(nE + 255) / 256, 256>>>(ei, nE);
    k_scan<<<1, 1024>>>(nN);
    k_fill<<<(nE + 255) / 256, 256>>>(nE);

    // step 1 remainder
    k_msg<<<nN, 128>>>();
    k_gru<<<(nN + 7) / 8, 256>>>(wih, whh, bih, bhh, out, nN);

    // steps 2..3
    for (int step = 1; step < 3; step++) {
        k_P<<<gP, 256, KP_SMEM>>>(nN);
        k_msg<<<nN, 128>>>();
        k_gru<<<(nN + 7) / 8, 256>>>(wih, whh, bih, bhh, out, nN);
    }
}